// round 6
// baseline (speedup 1.0000x reference)
#include <cuda_runtime.h>
#include <cuda_bf16.h>

#define NB     32
#define NZ     100
#define STATE  20
#define HIDN   128
#define HH     32
#define WW     32
#define STEPS  64
#define THRESH 0.1f

#define PIX    1024
#define IMG_SZ (STATE*PIX)
#define STATE_SZ (NB*IMG_SZ)
// block = 4 rows x 8 cols; 8 bands x 4 cols = 32 blocks/image
#define BPI    32
#define TOTBLK (NB*BPI)      // 1024

// ---------------- persistent device scratch ----------------
__device__ __align__(16) float g_S[STATE_SZ];
__device__ __align__(16) float g_T[STATE_SZ];
__device__ unsigned char      g_P  [NB*PIX];
__device__ unsigned char      g_HOT[TOTBLK];
__device__ unsigned char      g_NZ [TOTBLK];
__device__ __align__(16) float g_wp_pad[60*128*4];   // [cr=c*3+ky][h][4] (kx in slots 0..2)
__device__ __align__(16) float g_wu1Q  [32*128*4];   // [k>>2][h][4]  (k&3 in slots)

// ---------------- f32x2 helpers ----------------
__device__ __forceinline__ unsigned long long pack2(float v) {
    unsigned long long r; asm("mov.b64 %0, {%1, %1};" : "=l"(r) : "f"(v)); return r;
}
__device__ __forceinline__ void fma2(unsigned long long& d,
                                     unsigned long long a, unsigned long long b) {
    asm("fma.rn.f32x2 %0, %1, %2, %0;" : "+l"(d) : "l"(a), "l"(b));
}
__device__ __forceinline__ float2 unpack2(unsigned long long v) {
    float lo, hi; asm("mov.b64 {%0, %1}, %2;" : "=f"(lo), "=f"(hi) : "l"(v));
    return make_float2(lo, hi);
}

// ---------------- weight repack ----------------
__global__ void k_pack(const float* __restrict__ wp, const float* __restrict__ wu1)
{
    int i = blockIdx.x*256 + threadIdx.x;
    if (i < 128*180) {
        int h = i / 180, k = i % 180;            // k = c*9 + ky*3 + kx
        g_wp_pad[(k/3)*512 + h*4 + (k%3)] = wp[i];
    }
    if (i < 128*128) {
        int h = i >> 7, k = i & 127;
        g_wu1Q[(k>>2)*512 + h*4 + (k&3)] = wu1[i];
    }
}

// ---------------- zero state + flags ----------------
__global__ void k_zero()
{
    int i = blockIdx.x*256 + threadIdx.x;
    if (i < STATE_SZ) g_S[i] = 0.f;
    if (i < TOTBLK)   g_NZ[i] = 0;
}

// ---------------- init MLP ----------------
__global__ void k_init(const float* __restrict__ z,
                       const float* __restrict__ w1, const float* __restrict__ b1,
                       const float* __restrict__ w2, const float* __restrict__ b2)
{
    int n = blockIdx.x;
    int t = threadIdx.x;
    __shared__ float zz[NZ];
    __shared__ float h[50];
    if (t < NZ) zz[t] = z[n*NZ + t];
    __syncthreads();
    if (t < 50) {
        float a = b1[t];
        #pragma unroll 4
        for (int j = 0; j < NZ; j++) a = fmaf(w1[t*NZ + j], zz[j], a);
        h[t] = fmaxf(a, 0.f);
    }
    __syncthreads();
    const int ctr = 16*WW + 16;
    if (t < STATE-1) {
        float a = b2[t];
        #pragma unroll 5
        for (int j = 0; j < 50; j++) a = fmaf(w2[t*50 + j], h[j], a);
        g_S[n*IMG_SZ + (1+t)*PIX + ctr] = a;
    }
    if (t == STATE-1) {
        g_S[n*IMG_SZ + ctr] = 0.5f;
        // center pixel (16,16): band 4, col-strip 2 -> blk 18
        g_NZ[18*32 + n] = 1;
    }
}

// ---------------- step kernel 1: one CTA per 4x8 block, 256 threads ----------------
// thread t: h = t&127 (hid ch), ph = t>>7 (row-half: rows 2ph, 2ph+1 -> 16 px)
__global__ void __launch_bounds__(256)
k_step1(const float* __restrict__ bp,
        const float* __restrict__ bu1,
        const float* __restrict__ wu2, const float* __restrict__ bu2)
{
    __shared__ __align__(16) float patchA[20*6*12];   // rows y0-1..y0+4, cols x0-1..x0+9(+pad)
    __shared__ __align__(16) float patchB[20*6*12];   // shifted by 1 col
    __shared__ __align__(16) float sperc[128*36];     // [k][pp] stride 36
    __shared__ __align__(16) float sh2T[32*132];      // [pp][h] stride 132
    __shared__ int sflag;

    const int b    = blockIdx.x;          // 0..1023
    const int n    = b & 31;
    const int blk  = b >> 5;              // 0..31
    const int band = blk >> 2;
    const int sx   = blk & 3;
    const int y0   = band << 2;
    const int x0   = sx << 3;
    const int t    = threadIdx.x;
    const int lane = t & 31;

    // ---- hot test: dilate NZ over 3x3 block neighborhood ----
    if (t < 32) {
        int h1 = 0;
        if (lane < 9) {
            int dy = lane/3 - 1, ds = lane%3 - 1;
            int bb = band + dy, ss = sx + ds;
            if ((unsigned)bb < 8u && (unsigned)ss < 4u)
                h1 = g_NZ[(bb*4 + ss)*32 + n];
        }
        h1 = __any_sync(0xffffffffu, h1);
        if (lane == 0) {
            sflag = h1;
            g_HOT[b] = (unsigned char)h1;
        }
    }
    __syncthreads();
    if (!sflag) return;

    const float* __restrict__ Sn = g_S + n*IMG_SZ;
    float* __restrict__ Tn = g_T + n*IMG_SZ;

    // ---- load patch [20][6][12] + shifted copy ----
    for (int i = t; i < 20*6*12; i += 256) {
        int pr = i / 12, col = i - pr*12;     // pr = c*6 + r
        int c = pr / 6, r = pr - c*6;
        int yy = y0 - 1 + r, xx = x0 - 1 + col;
        float v = 0.f;
        if (col < 11 && (unsigned)yy < (unsigned)HH && (unsigned)xx < (unsigned)WW)
            v = Sn[c*PIX + yy*WW + xx];
        patchA[i] = v;
        if (col >= 1) patchB[i - 1] = v;
        else          patchB[pr*12 + 11] = 0.f;
    }
    __syncthreads();

    // ---- pre-mask for 32 block pixels ----
    if (t < 32) {
        int pr0 = t >> 3, pc0 = t & 7;
        float m = 0.f;
        #pragma unroll
        for (int r2 = 0; r2 < 3; r2++)
            #pragma unroll
            for (int c2 = 0; c2 < 3; c2++)
                m = fmaxf(m, patchA[(pr0 + r2)*12 + pc0 + c2]);
        g_P[n*PIX + (y0 + pr0)*WW + x0 + pc0] = (m > THRESH) ? 1 : 0;
    }

    const int h  = t & 127;
    const int ph = t >> 7;              // rows 2ph, 2ph+1

    // ---- perceive: 3x3 conv 20->128, 16 px per thread (8 f32x2 accs) ----
    unsigned long long acc[2][4];
    {
        unsigned long long b2v = pack2(__ldg(&bp[h]));
        #pragma unroll
        for (int rr = 0; rr < 2; rr++)
            #pragma unroll
            for (int j = 0; j < 4; j++) acc[rr][j] = b2v;
    }
    #pragma unroll 2
    for (int c = 0; c < STATE; c++) {
        #pragma unroll
        for (int ky = 0; ky < 3; ky++) {
            const float4 w4 = __ldg((const float4*)&g_wp_pad[((c*3 + ky)*128 + h)*4]);
            const unsigned long long W0 = pack2(w4.x);
            const unsigned long long W1 = pack2(w4.y);
            const unsigned long long W2 = pack2(w4.z);
            #pragma unroll
            for (int rr = 0; rr < 2; rr++) {
                const int base = (c*6 + ky + 2*ph + rr)*12;
                const ulonglong2 A0 = *(const ulonglong2*)&patchA[base];
                const ulonglong2 A1 = *(const ulonglong2*)&patchA[base + 4];
                const unsigned long long A2 = *(const unsigned long long*)&patchA[base + 8];
                const ulonglong2 B0 = *(const ulonglong2*)&patchB[base];
                const ulonglong2 B1 = *(const ulonglong2*)&patchB[base + 4];
                fma2(acc[rr][0], W0, A0.x); fma2(acc[rr][1], W0, A0.y);
                fma2(acc[rr][2], W0, A1.x); fma2(acc[rr][3], W0, A1.y);
                fma2(acc[rr][0], W1, B0.x); fma2(acc[rr][1], W1, B0.y);
                fma2(acc[rr][2], W1, B1.x); fma2(acc[rr][3], W1, B1.y);
                fma2(acc[rr][0], W2, A0.y); fma2(acc[rr][1], W2, A1.x);
                fma2(acc[rr][2], W2, A1.y); fma2(acc[rr][3], W2, A2);
            }
        }
    }
    #pragma unroll
    for (int rr = 0; rr < 2; rr++)
        #pragma unroll
        for (int j = 0; j < 4; j++)
            *(unsigned long long*)&sperc[h*36 + (2*ph + rr)*8 + 2*j] = acc[rr][j];
    __syncthreads();

    // ---- up1: 1x1 128->128 + relu, 16 px per thread ----
    unsigned long long a1[8];
    {
        unsigned long long b2v = pack2(__ldg(&bu1[h]));
        #pragma unroll
        for (int j = 0; j < 8; j++) a1[j] = b2v;
    }
    const int ppb = 16*ph;
    #pragma unroll 2
    for (int k4 = 0; k4 < 32; k4++) {
        const float4 w4 = __ldg((const float4*)&g_wu1Q[(k4*128 + h)*4]);
        const float wk[4] = {w4.x, w4.y, w4.z, w4.w};
        #pragma unroll
        for (int j = 0; j < 4; j++) {
            const int k = 4*k4 + j;
            const unsigned long long W = pack2(wk[j]);
            const ulonglong2 v0 = *(const ulonglong2*)&sperc[k*36 + ppb];
            const ulonglong2 v1 = *(const ulonglong2*)&sperc[k*36 + ppb + 4];
            const ulonglong2 v2 = *(const ulonglong2*)&sperc[k*36 + ppb + 8];
            const ulonglong2 v3 = *(const ulonglong2*)&sperc[k*36 + ppb + 12];
            fma2(a1[0], W, v0.x); fma2(a1[1], W, v0.y);
            fma2(a1[2], W, v1.x); fma2(a1[3], W, v1.y);
            fma2(a1[4], W, v2.x); fma2(a1[5], W, v2.y);
            fma2(a1[6], W, v3.x); fma2(a1[7], W, v3.y);
        }
    }
    #pragma unroll
    for (int j = 0; j < 8; j++) {
        float2 v = unpack2(a1[j]);
        sh2T[(ppb + 2*j + 0)*132 + h] = fmaxf(v.x, 0.f);
        sh2T[(ppb + 2*j + 1)*132 + h] = fmaxf(v.y, 0.f);
    }
    __syncthreads();

    // ---- up2: 1x1 128->20, T = S + upd (640 outputs over 256 threads) ----
    #pragma unroll
    for (int round = 0; round < 3; round++) {
        int i2 = t + round*256;
        if (i2 < 640) {
            int c = i2 >> 5, pp = i2 & 31;
            unsigned long long A0 = 0ull, A1 = 0ull;
            const ulonglong2* hv = (const ulonglong2*)&sh2T[pp*132];
            const ulonglong2* wv = (const ulonglong2*)&wu2[c*128];
            #pragma unroll 8
            for (int k4 = 0; k4 < 32; k4++) {
                const ulonglong2 h2 = hv[k4];
                const ulonglong2 w2 = __ldg(&wv[k4]);
                fma2(A0, w2.x, h2.x);
                fma2(A1, w2.y, h2.y);
            }
            float2 s0 = unpack2(A0), s1 = unpack2(A1);
            float a = __ldg(&bu2[c]) + ((s0.x + s0.y) + (s1.x + s1.y));
            int pr0 = pp >> 3, pc0 = pp & 7;
            Tn[c*PIX + (y0 + pr0)*WW + x0 + pc0] =
                patchA[(c*6 + pr0 + 1)*12 + pc0 + 1] + a;
        }
    }
}

// ---------------- step kernel 2: warp per block, post maxpool + masking ----------------
__global__ void __launch_bounds__(256)
k_step2()
{
    const int wid  = threadIdx.x >> 5;
    const int lane = threadIdx.x & 31;
    const int b    = blockIdx.x*8 + wid;     // block id 0..1023
    const int n    = b & 31;
    const int blk  = b >> 5;
    const int y0   = (blk >> 2) << 2;
    const int x0   = (blk & 3) << 3;

    unsigned char hot = g_HOT[b];
    unsigned char nz  = g_NZ[b];
    if (!(hot | nz)) return;

    const int y  = y0 + (lane >> 3);
    const int x  = x0 + (lane & 7);
    const int px = y*WW + x;
    const float* __restrict__ Tn = g_T + n*IMG_SZ;
    float* __restrict__ Sn = g_S + n*IMG_SZ;

    int alive = 0;
    if (hot && g_P[n*PIX + px]) {
        float m = -1.f;
        #pragma unroll
        for (int dy = -1; dy <= 1; dy++) {
            int yy = y + dy;
            if ((unsigned)yy >= (unsigned)HH) continue;
            #pragma unroll
            for (int dx = -1; dx <= 1; dx++) {
                int xx = x + dx;
                if ((unsigned)xx >= (unsigned)WW) continue;
                m = fmaxf(m, Tn[yy*WW + xx]);
            }
        }
        alive = (m > THRESH) ? 1 : 0;
    }
    unsigned bal = __ballot_sync(0xffffffffu, alive);

    if (hot) {
        #pragma unroll
        for (int c = 0; c < STATE; c++)
            Sn[c*PIX + px] = alive ? Tn[c*PIX + px] : 0.f;
        if (lane == 0) g_NZ[b] = bal ? 1 : 0;
    } else {
        #pragma unroll
        for (int c = 0; c < STATE; c++)
            Sn[c*PIX + px] = 0.f;
        if (lane == 0) g_NZ[b] = 0;
    }
}

// ---------------- extract output ----------------
__global__ void k_extract(float* __restrict__ out)
{
    int g = blockIdx.x*256 + threadIdx.x;
    int n = g >> 10, rem = g & 1023;
    out[g] = g_S[n*IMG_SZ + rem];
}

// ---------------- launch ----------------
extern "C" void kernel_launch(void* const* d_in, const int* in_sizes, int n_in,
                              void* d_out, int out_size)
{
    const float* z   = (const float*)d_in[0];
    const float* w1  = (const float*)d_in[1];
    const float* b1  = (const float*)d_in[2];
    const float* w2  = (const float*)d_in[3];
    const float* b2  = (const float*)d_in[4];
    const float* wp  = (const float*)d_in[5];
    const float* bp  = (const float*)d_in[6];
    const float* wu1 = (const float*)d_in[7];
    const float* bu1 = (const float*)d_in[8];
    const float* wu2 = (const float*)d_in[9];
    const float* bu2 = (const float*)d_in[10];
    float* out = (float*)d_out;

    k_pack<<<(128*180 + 255)/256, 256>>>(wp, wu1);
    k_zero<<<(STATE_SZ + 255)/256, 256>>>();
    k_init<<<NB, 128>>>(z, w1, b1, w2, b2);

    for (int s = 0; s < STEPS; s++) {
        k_step1<<<TOTBLK, 256>>>(bp, bu1, wu2, bu2);
        k_step2<<<TOTBLK/8, 256>>>();
    }
    k_extract<<<(NB*PIX)/256, 256>>>(out);
}